// round 1
// baseline (speedup 1.0000x reference)
#include <cuda_runtime.h>
#include <math.h>

// Problem constants
#define B_  256
#define S_  256
#define H_  512
#define H2_ 1024
#define O_  512

// Scratch (device globals; allocation APIs are forbidden)
__device__ float g_xe  [(size_t)S_ * B_ * H_ ];  // [S,B,H]  gathered embeddings
__device__ float g_Gx  [(size_t)S_ * B_ * H2_];  // [S,B,2H] x-part of gates + bg
__device__ float g_Cx  [(size_t)S_ * B_ * H_ ];  // [S,B,H]  x-part of candidate + bh
__device__ float g_hall[(size_t)S_ * B_ * H_ ];  // [S,B,H]  all hidden states
__device__ float g_h   [B_ * H_];                // current hidden
__device__ float g_z   [B_ * H_];                // update gate
__device__ float g_rh  [B_ * H_];                // r * h

// ---------------------------------------------------------------------------
// Tiled SGEMM mainloop: C[64x64] tile of A[M,K] @ Bw[N,K]^T
// 256 threads, each computes a 4x4 micro-tile. All dims are multiples of tiles.
// ---------------------------------------------------------------------------
#define BM 64
#define BN 64
#define BK 16

__device__ __forceinline__ void gemm_mainloop(
    const float* __restrict__ A, int lda,
    const float* __restrict__ Bw, int ldb,
    int K, float (&acc)[4][4])
{
    __shared__ float As[BK][BM];
    __shared__ float Bs[BK][BN];

    const int tid  = threadIdx.x;
    const int lrow = tid >> 2;          // 0..63  (tile row for loads)
    const int lk   = (tid & 3) << 2;    // 0,4,8,12 (k offset for loads)
    const int ty   = (tid >> 4) << 2;   // 0..60 step 4 (compute row base)
    const int tx   = (tid & 15) << 2;   // 0..60 step 4 (compute col base)
    const int m0   = blockIdx.y * BM;
    const int n0   = blockIdx.x * BN;

    #pragma unroll
    for (int i = 0; i < 4; i++)
        #pragma unroll
        for (int j = 0; j < 4; j++) acc[i][j] = 0.0f;

    const float* Ap = A  + (size_t)(m0 + lrow) * lda + lk;
    const float* Bp = Bw + (size_t)(n0 + lrow) * ldb + lk;

    for (int k0 = 0; k0 < K; k0 += BK) {
        float4 av = *(const float4*)(Ap + k0);
        float4 bv = *(const float4*)(Bp + k0);
        As[lk + 0][lrow] = av.x; As[lk + 1][lrow] = av.y;
        As[lk + 2][lrow] = av.z; As[lk + 3][lrow] = av.w;
        Bs[lk + 0][lrow] = bv.x; Bs[lk + 1][lrow] = bv.y;
        Bs[lk + 2][lrow] = bv.z; Bs[lk + 3][lrow] = bv.w;
        __syncthreads();

        #pragma unroll
        for (int k = 0; k < BK; k++) {
            float4 a4 = *(const float4*)&As[k][ty];
            float4 b4 = *(const float4*)&Bs[k][tx];
            float ar[4] = {a4.x, a4.y, a4.z, a4.w};
            float br[4] = {b4.x, b4.y, b4.z, b4.w};
            #pragma unroll
            for (int i = 0; i < 4; i++)
                #pragma unroll
                for (int j = 0; j < 4; j++)
                    acc[i][j] = fmaf(ar[i], br[j], acc[i][j]);
        }
        __syncthreads();
    }
}

// ---------------------------------------------------------------------------
// Kernels
// ---------------------------------------------------------------------------
__global__ void zero_h_kernel() {
    g_h[blockIdx.x * 256 + threadIdx.x] = 0.0f;
}

__global__ void gather_embed(const int* __restrict__ x,
                             const float* __restrict__ emb) {
    int idx = blockIdx.x * 256 + threadIdx.x;   // over S*B*(H/4)
    int h4  = idx & (H_ / 4 - 1);               // 0..127
    int row = idx >> 7;                         // s*B + b
    int b   = row & (B_ - 1);
    int s   = row >> 8;
    int tok = x[b * S_ + s];
    reinterpret_cast<float4*>(g_xe)[(size_t)row * (H_ / 4) + h4] =
        reinterpret_cast<const float4*>(emb)[(size_t)tok * (H_ / 4) + h4];
}

// mode 0: Gx = xe @ Wg[:, :H]^T + bg   (ldc = 2H)
// mode 1: Cx = xe @ Wh[:, :H]^T + bh   (ldc = H)
__global__ void sgemm_pre(const float* __restrict__ Bw, int ldb,
                          const float* __restrict__ bias, int mode) {
    float acc[4][4];
    gemm_mainloop(g_xe, H_, Bw, ldb, H_, acc);

    const int m0 = blockIdx.y * BM, n0 = blockIdx.x * BN;
    const int ty = (threadIdx.x >> 4) << 2, tx = (threadIdx.x & 15) << 2;
    float* C  = (mode == 0) ? g_Gx : g_Cx;
    int   ldc = (mode == 0) ? H2_ : H_;
    #pragma unroll
    for (int i = 0; i < 4; i++) {
        int m = m0 + ty + i;
        #pragma unroll
        for (int j = 0; j < 4; j++) {
            int n = n0 + tx + j;
            C[(size_t)m * ldc + n] = acc[i][j] + bias[n];
        }
    }
}

// gates: sigmoid(Gx[t] + h @ Wg[:, H:]^T) -> z and rh = r*h
__global__ void step_zr(const float* __restrict__ Wg, int t) {
    float acc[4][4];
    gemm_mainloop(g_h, H_, Wg + H_, H2_, H_, acc);

    const int m0 = blockIdx.y * BM, n0 = blockIdx.x * BN;
    const int ty = (threadIdx.x >> 4) << 2, tx = (threadIdx.x & 15) << 2;
    const float* Gxt = g_Gx + (size_t)t * B_ * H2_;
    #pragma unroll
    for (int i = 0; i < 4; i++) {
        int m = m0 + ty + i;
        #pragma unroll
        for (int j = 0; j < 4; j++) {
            int n = n0 + tx + j;
            float g = acc[i][j] + Gxt[(size_t)m * H2_ + n];
            float v = 1.0f / (1.0f + __expf(-g));
            if (n < H_) {
                g_z[m * H_ + n] = v;
            } else {
                int nn = n - H_;
                g_rh[m * H_ + nn] = v * g_h[m * H_ + nn];
            }
        }
    }
}

// candidate + state update: h = h + z*(tanh(Cx[t] + rh @ Wh[:, H:]^T) - h)
__global__ void step_h(const float* __restrict__ Wh, int t) {
    float acc[4][4];
    gemm_mainloop(g_rh, H_, Wh + H_, H2_, H_, acc);

    const int m0 = blockIdx.y * BM, n0 = blockIdx.x * BN;
    const int ty = (threadIdx.x >> 4) << 2, tx = (threadIdx.x & 15) << 2;
    const float* Cxt = g_Cx + (size_t)t * B_ * H_;
    float* hall_t = g_hall + (size_t)t * B_ * H_;
    #pragma unroll
    for (int i = 0; i < 4; i++) {
        int m = m0 + ty + i;
        #pragma unroll
        for (int j = 0; j < 4; j++) {
            int n = n0 + tx + j;
            float cand = tanhf(acc[i][j] + Cxt[m * H_ + n]);
            float z  = g_z[m * H_ + n];
            float hp = g_h[m * H_ + n];
            float hn = fmaf(z, cand - hp, hp);
            g_h[m * H_ + n] = hn;
            hall_t[m * H_ + n] = hn;
        }
    }
}

// ys[b,s,:] = h_all[s,b,:] @ Wo^T + bo
__global__ void sgemm_out(const float* __restrict__ Wo,
                          const float* __restrict__ bo,
                          float* __restrict__ yout) {
    float acc[4][4];
    gemm_mainloop(g_hall, H_, Wo, H_, H_, acc);

    const int m0 = blockIdx.y * BM, n0 = blockIdx.x * BN;
    const int ty = (threadIdx.x >> 4) << 2, tx = (threadIdx.x & 15) << 2;
    #pragma unroll
    for (int i = 0; i < 4; i++) {
        int m = m0 + ty + i;       // m = s*B + b
        int s = m >> 8;            // B_ == 256
        int b = m & (B_ - 1);
        #pragma unroll
        for (int j = 0; j < 4; j++) {
            int n = n0 + tx + j;
            yout[((size_t)b * S_ + s) * O_ + n] = acc[i][j] + bo[n];
        }
    }
}

__global__ void copy_hfinal(float* __restrict__ out) {
    int i = blockIdx.x * 256 + threadIdx.x;
    out[i] = g_h[i];
}

// ---------------------------------------------------------------------------
extern "C" void kernel_launch(void* const* d_in, const int* in_sizes, int n_in,
                              void* d_out, int out_size) {
    (void)in_sizes; (void)n_in; (void)out_size;
    const int*   x   = (const int*)  d_in[0];
    const float* emb = (const float*)d_in[1];
    const float* Wg  = (const float*)d_in[2];   // [2H, 2H]
    const float* bg  = (const float*)d_in[3];   // [2H]
    const float* Wh  = (const float*)d_in[4];   // [H, 2H]
    const float* bh  = (const float*)d_in[5];   // [H]
    const float* Wo  = (const float*)d_in[6];   // [O, H]
    const float* bo  = (const float*)d_in[7];   // [O]
    float* out = (float*)d_out;                 // [B*H] h_final, then [B,S,O] ys

    zero_h_kernel<<<(B_ * H_) / 256, 256>>>();
    gather_embed<<<(S_ * B_ * (H_ / 4)) / 256, 256>>>(x, emb);

    // x-dependent halves of gate / candidate pre-activations (big GEMMs)
    sgemm_pre<<<dim3(H2_ / BN, (S_ * B_) / BM), 256>>>(Wg, H2_, bg, 0);
    sgemm_pre<<<dim3(H_  / BN, (S_ * B_) / BM), 256>>>(Wh, H2_, bh, 1);

    // serial recurrence
    for (int t = 0; t < S_; t++) {
        step_zr<<<dim3(H2_ / BN, B_ / BM), 256>>>(Wg, t);
        step_h <<<dim3(H_  / BN, B_ / BM), 256>>>(Wh, t);
    }

    // deferred output projection over all timesteps (big GEMM)
    sgemm_out<<<dim3(O_ / BN, (S_ * B_) / BM), 256>>>(Wo, bo, out + (size_t)B_ * H_);
    copy_hfinal<<<(B_ * H_) / 256, 256>>>(out);
}

// round 2
// speedup vs baseline: 1.9497x; 1.9497x over previous
#include <cuda_runtime.h>
#include <math.h>

// Problem constants
#define B_  256
#define S_  256
#define H_  512
#define H2_ 1024
#define O_  512

// ---------------------------------------------------------------------------
// Scratch (device globals; allocation APIs are forbidden)
// ---------------------------------------------------------------------------
__device__ float g_xe  [(size_t)S_ * B_ * H_ ];  // [S,B,H]  gathered embeddings
__device__ float g_Gx  [(size_t)S_ * B_ * H2_];  // [S,B,2H] x-part of gates + bg
__device__ float g_Cx  [(size_t)S_ * B_ * H_ ];  // [S,B,H]  x-part of candidate + bh
__device__ float g_hall[(size_t)S_ * B_ * H_ ];  // [S,B,H]  all hidden states
__device__ float g_h   [B_ * H_];                // current hidden
__device__ float g_z   [B_ * H_];                // update gate
__device__ float g_rh  [B_ * H_];                // r * h

__device__ unsigned g_bar_cnt = 0;
__device__ unsigned g_bar_gen = 0;

// ---------------------------------------------------------------------------
// f32x2 packed FMA helpers (FFMA2 path — 2x fp32 FMA throughput on sm_100+)
// ---------------------------------------------------------------------------
typedef unsigned long long ull;

#define FMA2(d, a, b) \
    asm("fma.rn.f32x2 %0, %1, %2, %3;" : "=l"(d) : "l"(a), "l"(b), "l"(d))

__device__ __forceinline__ ull splat2(float x) {
    ull d;
    asm("mov.b64 %0, {%1, %1};" : "=l"(d) : "r"(__float_as_uint(x)));
    return d;
}
__device__ __forceinline__ float2 unpack2(ull v) {
    float2 r;
    asm("mov.b64 {%0, %1}, %2;" : "=f"(r.x), "=f"(r.y) : "l"(v));
    return r;
}

// ---------------------------------------------------------------------------
// Software grid barrier (all blocks resident in one wave)
// ---------------------------------------------------------------------------
__device__ __forceinline__ void grid_sync() {
    __syncthreads();
    if (threadIdx.x == 0) {
        volatile unsigned* genp = &g_bar_gen;
        unsigned gen = *genp;
        __threadfence();
        if (atomicAdd(&g_bar_cnt, 1u) == gridDim.x - 1) {
            *(volatile unsigned*)&g_bar_cnt = 0;
            __threadfence();
            *genp = gen + 1;
        } else {
            while (*genp == gen) { }
        }
        __threadfence();
    }
    __syncthreads();
}

// ---------------------------------------------------------------------------
// Big SGEMM: C[M=65536, N] = A[M,512] @ Bw[N,512]^T + bias
// 128x128 tile, 256 threads, 8x8 micro-tile, f32x2 packed FMAs.
// Asel: 0 -> g_xe, 1 -> g_hall
// mode: 0 -> g_Gx (ldc=1024), 1 -> g_Cx (ldc=512), 2 -> yout with (b,s) remap
// ---------------------------------------------------------------------------
#define TBM 128
#define TBN 128
#define TBK 16
#define LDT 132   // padded smem row (floats): 132*4 = 528 = 33*16, keeps 16B align

__global__ __launch_bounds__(256, 2)
void sgemm_big(int Asel, const float* __restrict__ Bw, int ldb,
               const float* __restrict__ bias, int mode,
               float* __restrict__ yout) {
    __shared__ float As[TBK * LDT];
    __shared__ float Bs[TBK * LDT];

    const int tid = threadIdx.x;
    const int ty  = tid >> 4;          // 0..15 -> rows ty*8..+7
    const int tx  = tid & 15;          // 0..15 -> cols tx*8..+7
    const int m0  = blockIdx.y * TBM;
    const int n0  = blockIdx.x * TBN;

    const float* A = Asel ? g_hall : g_xe;

    ull acc[4][8];
    #pragma unroll
    for (int i = 0; i < 4; i++)
        #pragma unroll
        for (int j = 0; j < 8; j++) acc[i][j] = 0ull;

    for (int k0 = 0; k0 < H_; k0 += TBK) {
        // load A tile 128x16 and B tile 128x16, transposed into [k][mn]
        #pragma unroll
        for (int it = 0; it < 2; it++) {
            int idx = tid + it * 256;      // 0..511
            int r   = idx >> 2;            // 0..127
            int kq  = idx & 3;             // 0..3
            float4 av = *(const float4*)(A  + (size_t)(m0 + r) * H_ + k0 + kq * 4);
            float4 bv = *(const float4*)(Bw + (size_t)(n0 + r) * ldb + k0 + kq * 4);
            As[(kq * 4 + 0) * LDT + r] = av.x;
            As[(kq * 4 + 1) * LDT + r] = av.y;
            As[(kq * 4 + 2) * LDT + r] = av.z;
            As[(kq * 4 + 3) * LDT + r] = av.w;
            Bs[(kq * 4 + 0) * LDT + r] = bv.x;
            Bs[(kq * 4 + 1) * LDT + r] = bv.y;
            Bs[(kq * 4 + 2) * LDT + r] = bv.z;
            Bs[(kq * 4 + 3) * LDT + r] = bv.w;
        }
        __syncthreads();

        #pragma unroll
        for (int kk = 0; kk < TBK; kk++) {
            // a: 8 consecutive m (4 packed pairs), b: 8 n scalars
            ulonglong2 a01 = *(const ulonglong2*)&As[kk * LDT + ty * 8];
            ulonglong2 a23 = *(const ulonglong2*)&As[kk * LDT + ty * 8 + 4];
            float4 bl = *(const float4*)&Bs[kk * LDT + tx * 8];
            float4 bh4 = *(const float4*)&Bs[kk * LDT + tx * 8 + 4];
            ull ap[4] = {a01.x, a01.y, a23.x, a23.y};
            float bsc[8] = {bl.x, bl.y, bl.z, bl.w, bh4.x, bh4.y, bh4.z, bh4.w};
            #pragma unroll
            for (int j = 0; j < 8; j++) {
                ull bb = splat2(bsc[j]);
                #pragma unroll
                for (int i = 0; i < 4; i++) FMA2(acc[i][j], ap[i], bb);
            }
        }
        __syncthreads();
    }

    // epilogue
    #pragma unroll
    for (int i = 0; i < 4; i++) {
        #pragma unroll
        for (int j = 0; j < 8; j++) {
            float2 v = unpack2(acc[i][j]);
            int n  = n0 + tx * 8 + j;
            float bval = bias[n];
            int mA = m0 + ty * 8 + i * 2;
            int mB = mA + 1;
            float oA = v.x + bval, oB = v.y + bval;
            if (mode == 0) {
                g_Gx[(size_t)mA * H2_ + n] = oA;
                g_Gx[(size_t)mB * H2_ + n] = oB;
            } else if (mode == 1) {
                g_Cx[(size_t)mA * H_ + n] = oA;
                g_Cx[(size_t)mB * H_ + n] = oB;
            } else {
                int sA = mA >> 8, bA = mA & 255;
                int sB = mB >> 8, bB = mB & 255;
                yout[((size_t)bA * S_ + sA) * O_ + n] = oA;
                yout[((size_t)bB * S_ + sB) * O_ + n] = oB;
            }
        }
    }
}

// ---------------------------------------------------------------------------
// Persistent recurrent kernel.
// Grid = 128 blocks (one wave), 256 threads.
// Block (mt = bid>>4, nt = bid&15):
//   gate tile:      m in [mt*32, +32), gate-n in [nt*64, +64) of 1024
//   candidate tile: m in [mt*32, +32), n in [nt*32, +32) of 512
// Weight slices cached in SMEM for all 256 steps:
//   Wgs[k][j]  (512 x 64, pad 68)  = Wg[nt*64+j][512+k]
//   Whs[k][j]  (512 x 32, pad 36)  = Wh[nt*32+j][512+k]
//   APan[k][m] (128 x 32, pad 34)  = activation panel (h or rh)
// ---------------------------------------------------------------------------
#define WGS_LD 68
#define WHS_LD 36
#define AP_LD  34
#define WGS_OFF 0
#define WHS_OFF (512 * WGS_LD)                 // 34816
#define AP_OFF  (WHS_OFF + 512 * WHS_LD)       // 53248
#define PERSIST_SMEM ((AP_OFF + 128 * AP_LD) * 4)  // 230400 bytes

__global__ __launch_bounds__(256, 1)
void gru_persist(const float* __restrict__ Wg, const float* __restrict__ Wh) {
    extern __shared__ float sm[];
    float* Wgs  = sm + WGS_OFF;
    float* Whs  = sm + WHS_OFF;
    float* APan = sm + AP_OFF;

    const int tid = threadIdx.x;
    const int bid = blockIdx.x;
    const int mt  = bid >> 4;      // 0..7
    const int nt  = bid & 15;      // 0..15
    const int ty  = tid >> 4;      // 0..15 -> m = ty*2, +1
    const int tx  = tid & 15;      // 0..15

    // ---- init: zero h, load weight slices ----
    {
        int base = (bid * 256 + tid) * 4;    // 128*256*4 = 131072 = B*H
        *(float4*)&g_h[base] = make_float4(0.f, 0.f, 0.f, 0.f);
    }
    for (int idx = tid; idx < 64 * 128; idx += 256) {   // Wg slice: 64 rows x 128 f4
        int j  = idx >> 7;
        int k4 = idx & 127;
        float4 v = *(const float4*)(Wg + (size_t)(nt * 64 + j) * H2_ + H_ + k4 * 4);
        Wgs[(k4 * 4 + 0) * WGS_LD + j] = v.x;
        Wgs[(k4 * 4 + 1) * WGS_LD + j] = v.y;
        Wgs[(k4 * 4 + 2) * WGS_LD + j] = v.z;
        Wgs[(k4 * 4 + 3) * WGS_LD + j] = v.w;
    }
    for (int idx = tid; idx < 32 * 128; idx += 256) {   // Wh slice: 32 rows x 128 f4
        int j  = idx >> 7;
        int k4 = idx & 127;
        float4 v = *(const float4*)(Wh + (size_t)(nt * 32 + j) * H2_ + H_ + k4 * 4);
        Whs[(k4 * 4 + 0) * WHS_LD + j] = v.x;
        Whs[(k4 * 4 + 1) * WHS_LD + j] = v.y;
        Whs[(k4 * 4 + 2) * WHS_LD + j] = v.z;
        Whs[(k4 * 4 + 3) * WHS_LD + j] = v.w;
    }
    grid_sync();

    const float* hrow  = g_h  + (size_t)mt * 32 * H_;
    const float* rhrow = g_rh + (size_t)mt * 32 * H_;

    for (int t = 0; t < S_; t++) {
        // ================= gate phase: z / rh =================
        ull acc[2][2] = {{0ull, 0ull}, {0ull, 0ull}};   // [m-local][n-pair]
        for (int kp = 0; kp < 4; kp++) {
            // load h panel 32m x 128k
            #pragma unroll
            for (int it = 0; it < 4; it++) {
                int idx = tid + it * 256;    // 0..1023 float4s
                int m  = idx >> 5;
                int k4 = idx & 31;
                float4 v = *(const float4*)(hrow + (size_t)m * H_ + kp * 128 + k4 * 4);
                APan[(k4 * 4 + 0) * AP_LD + m] = v.x;
                APan[(k4 * 4 + 1) * AP_LD + m] = v.y;
                APan[(k4 * 4 + 2) * AP_LD + m] = v.z;
                APan[(k4 * 4 + 3) * AP_LD + m] = v.w;
            }
            __syncthreads();
            const float* wbase = Wgs + (size_t)kp * 128 * WGS_LD + tx * 4;
            #pragma unroll 16
            for (int kk = 0; kk < 128; kk++) {
                float2 a = *(const float2*)&APan[kk * AP_LD + ty * 2];
                ulonglong2 b = *(const ulonglong2*)(wbase + kk * WGS_LD);
                ull a0 = splat2(a.x), a1 = splat2(a.y);
                FMA2(acc[0][0], a0, b.x);
                FMA2(acc[0][1], a0, b.y);
                FMA2(acc[1][0], a1, b.x);
                FMA2(acc[1][1], a1, b.y);
            }
            __syncthreads();
        }
        {
            const float* Gxt = g_Gx + (size_t)t * B_ * H2_;
            int n_base = nt * 64 + tx * 4;
            #pragma unroll
            for (int i = 0; i < 2; i++) {
                int m = mt * 32 + ty * 2 + i;
                #pragma unroll
                for (int p = 0; p < 2; p++) {
                    float2 v = unpack2(acc[i][p]);
                    float vs[2] = {v.x, v.y};
                    #pragma unroll
                    for (int c = 0; c < 2; c++) {
                        int n = n_base + p * 2 + c;
                        float gv  = vs[c] + Gxt[(size_t)m * H2_ + n];
                        float sig = 1.0f / (1.0f + __expf(-gv));
                        if (nt < 8) {
                            g_z[m * H_ + n] = sig;
                        } else {
                            int n2 = n - H_;
                            g_rh[m * H_ + n2] = sig * g_h[m * H_ + n2];
                        }
                    }
                }
            }
        }
        grid_sync();

        // ================= candidate phase: h update =================
        ull cacc[2] = {0ull, 0ull};    // [m-local], n-pair at tx*2
        for (int kp = 0; kp < 4; kp++) {
            #pragma unroll
            for (int it = 0; it < 4; it++) {
                int idx = tid + it * 256;
                int m  = idx >> 5;
                int k4 = idx & 31;
                float4 v = *(const float4*)(rhrow + (size_t)m * H_ + kp * 128 + k4 * 4);
                APan[(k4 * 4 + 0) * AP_LD + m] = v.x;
                APan[(k4 * 4 + 1) * AP_LD + m] = v.y;
                APan[(k4 * 4 + 2) * AP_LD + m] = v.z;
                APan[(k4 * 4 + 3) * AP_LD + m] = v.w;
            }
            __syncthreads();
            const float* wbase = Whs + (size_t)kp * 128 * WHS_LD + tx * 2;
            #pragma unroll 16
            for (int kk = 0; kk < 128; kk++) {
                float2 a = *(const float2*)&APan[kk * AP_LD + ty * 2];
                ull b = *(const ull*)(wbase + kk * WHS_LD);
                FMA2(cacc[0], splat2(a.x), b);
                FMA2(cacc[1], splat2(a.y), b);
            }
            __syncthreads();
        }
        {
            const float* Cxt = g_Cx + (size_t)t * B_ * H_;
            float* hall_t = g_hall + (size_t)t * B_ * H_;
            int n_base = nt * 32 + tx * 2;
            #pragma unroll
            for (int i = 0; i < 2; i++) {
                int m = mt * 32 + ty * 2 + i;
                float2 v = unpack2(cacc[i]);
                float vs[2] = {v.x, v.y};
                #pragma unroll
                for (int c = 0; c < 2; c++) {
                    int n = n_base + c;
                    float cand = tanhf(vs[c] + Cxt[(size_t)m * H_ + n]);
                    float z  = g_z[m * H_ + n];
                    float hp = g_h[m * H_ + n];
                    float hn = fmaf(z, cand - hp, hp);
                    g_h[m * H_ + n]   = hn;
                    hall_t[(size_t)m * H_ + n] = hn;
                }
            }
        }
        grid_sync();
    }
}

// ---------------------------------------------------------------------------
__global__ void gather_embed(const int* __restrict__ x,
                             const float* __restrict__ emb) {
    int idx = blockIdx.x * 256 + threadIdx.x;   // over S*B*(H/4)
    int h4  = idx & (H_ / 4 - 1);               // 0..127
    int row = idx >> 7;                         // s*B + b
    int b   = row & (B_ - 1);
    int s   = row >> 8;
    int tok = x[b * S_ + s];
    reinterpret_cast<float4*>(g_xe)[(size_t)row * (H_ / 4) + h4] =
        reinterpret_cast<const float4*>(emb)[(size_t)tok * (H_ / 4) + h4];
}

__global__ void copy_hfinal(float* __restrict__ out) {
    int i = blockIdx.x * 256 + threadIdx.x;
    out[i] = g_h[i];
}

// ---------------------------------------------------------------------------
extern "C" void kernel_launch(void* const* d_in, const int* in_sizes, int n_in,
                              void* d_out, int out_size) {
    (void)in_sizes; (void)n_in; (void)out_size;
    const int*   x   = (const int*)  d_in[0];
    const float* emb = (const float*)d_in[1];
    const float* Wg  = (const float*)d_in[2];   // [2H, 2H]
    const float* bg  = (const float*)d_in[3];   // [2H]
    const float* Wh  = (const float*)d_in[4];   // [H, 2H]
    const float* bh  = (const float*)d_in[5];   // [H]
    const float* Wo  = (const float*)d_in[6];   // [O, H]
    const float* bo  = (const float*)d_in[7];   // [O]
    float* out = (float*)d_out;                 // [B*H] h_final, then [B,S,O] ys

    static int smem_set = 0;
    if (!smem_set) {
        cudaFuncSetAttribute(gru_persist,
                             cudaFuncAttributeMaxDynamicSharedMemorySize,
                             PERSIST_SMEM);
        smem_set = 1;
    }

    gather_embed<<<(S_ * B_ * (H_ / 4)) / 256, 256>>>(x, emb);

    // x-dependent halves of gate / candidate pre-activations (big GEMMs)
    sgemm_big<<<dim3(H2_ / TBN, (S_ * B_) / TBM), 256>>>(0, Wg, H2_, bg, 0, nullptr);
    sgemm_big<<<dim3(H_  / TBN, (S_ * B_) / TBM), 256>>>(0, Wh, H2_, bh, 1, nullptr);

    // persistent serial recurrence (one launch, 256 steps inside)
    gru_persist<<<128, 256, PERSIST_SMEM>>>(Wg, Wh);

    // deferred output projection over all timesteps (big GEMM)
    sgemm_big<<<dim3(O_ / TBN, (S_ * B_) / TBM), 256>>>(1, Wo, O_ == H_ ? H_ : H_, bo, 2,
                                                        out + (size_t)B_ * H_);
    copy_hfinal<<<(B_ * H_) / 256, 256>>>(out);
}

// round 3
// speedup vs baseline: 2.3319x; 1.1960x over previous
#include <cuda_runtime.h>
#include <math.h>

// Problem constants
#define B_  256
#define S_  256
#define H_  512
#define H2_ 1024
#define O_  512

// ---------------------------------------------------------------------------
// Scratch (device globals)
// ---------------------------------------------------------------------------
__device__ float g_xe  [(size_t)S_ * B_ * H_ ];
__device__ float g_Gx  [(size_t)S_ * B_ * H2_];
__device__ float g_Cx  [(size_t)S_ * B_ * H_ ];
__device__ float g_hall[(size_t)S_ * B_ * H_ ];
__device__ float g_h   [B_ * H_];
__device__ float g_z   [B_ * H_];
__device__ float g_rh  [B_ * H_];

__device__ unsigned g_bar_cnt = 0;
__device__ unsigned g_bar_gen = 0;

// ---------------------------------------------------------------------------
// f32x2 packed FMA helpers
// ---------------------------------------------------------------------------
typedef unsigned long long ull;

#define FMA2(d, a, b) \
    asm("fma.rn.f32x2 %0, %1, %2, %3;" : "=l"(d) : "l"(a), "l"(b), "l"(d))

__device__ __forceinline__ ull splat2(float x) {
    ull d;
    asm("mov.b64 %0, {%1, %1};" : "=l"(d) : "r"(__float_as_uint(x)));
    return d;
}
__device__ __forceinline__ float2 unpack2(ull v) {
    float2 r;
    asm("mov.b64 {%0, %1}, %2;" : "=f"(r.x), "=f"(r.y) : "l"(v));
    return r;
}

__device__ __forceinline__ float sigm(float x) {
    return __fdividef(1.0f, 1.0f + __expf(-x));
}
__device__ __forceinline__ float tanh_fast(float x) {
    return 1.0f - 2.0f * __fdividef(1.0f, __expf(2.0f * x) + 1.0f);
}

// ---------------------------------------------------------------------------
// Software grid barrier (all 128 blocks resident)
// ---------------------------------------------------------------------------
__device__ __forceinline__ void grid_sync() {
    __syncthreads();
    if (threadIdx.x == 0) {
        volatile unsigned* genp = &g_bar_gen;
        unsigned gen = *genp;
        __threadfence();
        if (atomicAdd(&g_bar_cnt, 1u) == gridDim.x - 1) {
            *(volatile unsigned*)&g_bar_cnt = 0;
            __threadfence();
            *genp = gen + 1;
        } else {
            while (*genp == gen) { }
        }
        __threadfence();
    }
    __syncthreads();
}

// ---------------------------------------------------------------------------
// Big SGEMM (unchanged from round 2): C[M,N] = A[M,512] @ Bw[N,512]^T + bias
// ---------------------------------------------------------------------------
#define TBM 128
#define TBN 128
#define TBK 16
#define LDT 132

__global__ __launch_bounds__(256, 2)
void sgemm_big(int Asel, const float* __restrict__ Bw, int ldb,
               const float* __restrict__ bias, int mode,
               float* __restrict__ yout) {
    __shared__ float As[TBK * LDT];
    __shared__ float Bs[TBK * LDT];

    const int tid = threadIdx.x;
    const int ty  = tid >> 4;
    const int tx  = tid & 15;
    const int m0  = blockIdx.y * TBM;
    const int n0  = blockIdx.x * TBN;

    const float* A = Asel ? g_hall : g_xe;

    ull acc[4][8];
    #pragma unroll
    for (int i = 0; i < 4; i++)
        #pragma unroll
        for (int j = 0; j < 8; j++) acc[i][j] = 0ull;

    for (int k0 = 0; k0 < H_; k0 += TBK) {
        #pragma unroll
        for (int it = 0; it < 2; it++) {
            int idx = tid + it * 256;
            int r   = idx >> 2;
            int kq  = idx & 3;
            float4 av = *(const float4*)(A  + (size_t)(m0 + r) * H_ + k0 + kq * 4);
            float4 bv = *(const float4*)(Bw + (size_t)(n0 + r) * ldb + k0 + kq * 4);
            As[(kq * 4 + 0) * LDT + r] = av.x;
            As[(kq * 4 + 1) * LDT + r] = av.y;
            As[(kq * 4 + 2) * LDT + r] = av.z;
            As[(kq * 4 + 3) * LDT + r] = av.w;
            Bs[(kq * 4 + 0) * LDT + r] = bv.x;
            Bs[(kq * 4 + 1) * LDT + r] = bv.y;
            Bs[(kq * 4 + 2) * LDT + r] = bv.z;
            Bs[(kq * 4 + 3) * LDT + r] = bv.w;
        }
        __syncthreads();

        #pragma unroll
        for (int kk = 0; kk < TBK; kk++) {
            ulonglong2 a01 = *(const ulonglong2*)&As[kk * LDT + ty * 8];
            ulonglong2 a23 = *(const ulonglong2*)&As[kk * LDT + ty * 8 + 4];
            float4 bl  = *(const float4*)&Bs[kk * LDT + tx * 8];
            float4 bh4 = *(const float4*)&Bs[kk * LDT + tx * 8 + 4];
            ull ap[4] = {a01.x, a01.y, a23.x, a23.y};
            float bsc[8] = {bl.x, bl.y, bl.z, bl.w, bh4.x, bh4.y, bh4.z, bh4.w};
            #pragma unroll
            for (int j = 0; j < 8; j++) {
                ull bb = splat2(bsc[j]);
                #pragma unroll
                for (int i = 0; i < 4; i++) FMA2(acc[i][j], ap[i], bb);
            }
        }
        __syncthreads();
    }

    #pragma unroll
    for (int i = 0; i < 4; i++) {
        #pragma unroll
        for (int j = 0; j < 8; j++) {
            float2 v = unpack2(acc[i][j]);
            int n  = n0 + tx * 8 + j;
            float bval = bias[n];
            int mA = m0 + ty * 8 + i * 2;
            int mB = mA + 1;
            float oA = v.x + bval, oB = v.y + bval;
            if (mode == 0) {
                g_Gx[(size_t)mA * H2_ + n] = oA;
                g_Gx[(size_t)mB * H2_ + n] = oB;
            } else if (mode == 1) {
                g_Cx[(size_t)mA * H_ + n] = oA;
                g_Cx[(size_t)mB * H_ + n] = oB;
            } else {
                int sA = mA >> 8, bA = mA & 255;
                int sB = mB >> 8, bB = mB & 255;
                yout[((size_t)bA * S_ + sA) * O_ + n] = oA;
                yout[((size_t)bB * S_ + sB) * O_ + n] = oB;
            }
        }
    }
}

// ---------------------------------------------------------------------------
// Persistent recurrent kernel, 128 blocks x 256 threads.
// Block (mt=bid>>4, nt=bid&15):
//   gate tile:  m [mt*32,+32), n [nt*64,+64) of 1024; thread tile 2m x 4n
//   cand tile:  m [mt*32,+32), n [nt*32,+32) of 512;  thread tile 2m x 2n
// Weights cached in smem (transposed, k-major rows):
//   Wgs: [512k][64n]  LD=64   (reads: 16 distinct 16B -> conflict-free)
//   Whs: [512k][32n]  LD=32
// Activation panel double-buffered in 64-k chunks: AP [64k][32m] LD=34.
// ---------------------------------------------------------------------------
#define WGS_LD 64
#define WHS_LD 32
#define APL    34
#define WGS_OFF 0
#define WHS_OFF (512 * WGS_LD)             // 32768 floats
#define AP_OFF  (WHS_OFF + 512 * WHS_LD)   // 49152 floats
#define AP_BUF  (64 * APL)                 // 2176 floats
#define PERSIST_SMEM ((AP_OFF + 2 * AP_BUF) * 4)   // 214016 bytes

__global__ __launch_bounds__(256, 1)
void gru_persist(const float* __restrict__ Wg, const float* __restrict__ Wh) {
    extern __shared__ float sm[];
    float* Wgs = sm + WGS_OFF;
    float* Whs = sm + WHS_OFF;
    float* AP  = sm + AP_OFF;

    const int tid = threadIdx.x;
    const int bid = blockIdx.x;
    const int mt  = bid >> 4;
    const int nt  = bid & 15;
    const int ty  = tid >> 4;      // m-pair index: rows ty*2, ty*2+1
    const int tx  = tid & 15;

    // init: zero h, load weight slices
    {
        int base = (bid * 256 + tid) * 4;
        *(float4*)&g_h[base] = make_float4(0.f, 0.f, 0.f, 0.f);
    }
    for (int idx = tid; idx < 64 * 128; idx += 256) {
        int j  = idx >> 7;
        int k4 = idx & 127;
        float4 v = *(const float4*)(Wg + (size_t)(nt * 64 + j) * H2_ + H_ + k4 * 4);
        Wgs[(k4 * 4 + 0) * WGS_LD + j] = v.x;
        Wgs[(k4 * 4 + 1) * WGS_LD + j] = v.y;
        Wgs[(k4 * 4 + 2) * WGS_LD + j] = v.z;
        Wgs[(k4 * 4 + 3) * WGS_LD + j] = v.w;
    }
    for (int idx = tid; idx < 32 * 128; idx += 256) {
        int j  = idx >> 7;
        int k4 = idx & 127;
        float4 v = *(const float4*)(Wh + (size_t)(nt * 32 + j) * H2_ + H_ + k4 * 4);
        Whs[(k4 * 4 + 0) * WHS_LD + j] = v.x;
        Whs[(k4 * 4 + 1) * WHS_LD + j] = v.y;
        Whs[(k4 * 4 + 2) * WHS_LD + j] = v.z;
        Whs[(k4 * 4 + 3) * WHS_LD + j] = v.w;
    }
    grid_sync();

    const float* hrow  = g_h  + (size_t)mt * 32 * H_;
    const float* rhrow = g_rh + (size_t)mt * 32 * H_;

    // per-thread panel-load coords (two float4 loads per chunk)
    const int pm0 = tid >> 4;            // 0..15
    const int pk0 = (tid & 15) * 4;      // 0..60
    const int pm1 = pm0 + 16;            // 16..31
    const int m0g = mt * 32 + ty * 2;    // global m for this thread's outputs
    const int nbg = nt * 64 + tx * 4;    // gate n base
    const int nbc = nt * 32 + tx * 2;    // cand n base

    for (int t = 0; t < S_; t++) {
        // ===================== GATE PHASE =====================
        // preload chunk 0 + epilogue operands
        float4 pf0 = __ldcg((const float4*)(hrow + (size_t)pm0 * H_ + pk0));
        float4 pf1 = __ldcg((const float4*)(hrow + (size_t)pm1 * H_ + pk0));
        const float* Gxt = g_Gx + (size_t)t * B_ * H2_;
        float4 gx0 = __ldcg((const float4*)(Gxt + (size_t)m0g * H2_ + nbg));
        float4 gx1 = __ldcg((const float4*)(Gxt + (size_t)(m0g + 1) * H2_ + nbg));
        float4 hv0 = make_float4(0.f,0.f,0.f,0.f), hv1 = hv0;
        if (nt >= 8) {
            int n2 = nbg - H_;
            hv0 = __ldcg((const float4*)(g_h + m0g * H_ + n2));
            hv1 = __ldcg((const float4*)(g_h + (m0g + 1) * H_ + n2));
        }

        ull a00 = 0ull, a01 = 0ull, a10 = 0ull, a11 = 0ull;
        #pragma unroll 1
        for (int c = 0; c < 8; c++) {
            float* buf = AP + (c & 1) * AP_BUF;
            {
                int kq = pk0 >> 2;
                buf[(kq * 4 + 0) * APL + pm0] = pf0.x;
                buf[(kq * 4 + 1) * APL + pm0] = pf0.y;
                buf[(kq * 4 + 2) * APL + pm0] = pf0.z;
                buf[(kq * 4 + 3) * APL + pm0] = pf0.w;
                buf[(kq * 4 + 0) * APL + pm1] = pf1.x;
                buf[(kq * 4 + 1) * APL + pm1] = pf1.y;
                buf[(kq * 4 + 2) * APL + pm1] = pf1.z;
                buf[(kq * 4 + 3) * APL + pm1] = pf1.w;
            }
            __syncthreads();
            if (c < 7) {
                int ko = (c + 1) * 64 + pk0;
                pf0 = __ldcg((const float4*)(hrow + (size_t)pm0 * H_ + ko));
                pf1 = __ldcg((const float4*)(hrow + (size_t)pm1 * H_ + ko));
            }
            const float* wb = Wgs + (size_t)c * 64 * WGS_LD + tx * 4;
            const float* ab = buf + ty * 2;
            #pragma unroll 16
            for (int kk = 0; kk < 64; kk++) {
                float2 a = *(const float2*)(ab + kk * APL);
                ulonglong2 b = *(const ulonglong2*)(wb + kk * WGS_LD);
                ull s0 = splat2(a.x), s1 = splat2(a.y);
                FMA2(a00, s0, b.x); FMA2(a01, s0, b.y);
                FMA2(a10, s1, b.x); FMA2(a11, s1, b.y);
            }
        }
        // gate epilogue
        {
            float2 v00 = unpack2(a00), v01 = unpack2(a01);
            float2 v10 = unpack2(a10), v11 = unpack2(a11);
            float4 r0 = make_float4(sigm(v00.x + gx0.x), sigm(v00.y + gx0.y),
                                    sigm(v01.x + gx0.z), sigm(v01.y + gx0.w));
            float4 r1 = make_float4(sigm(v10.x + gx1.x), sigm(v10.y + gx1.y),
                                    sigm(v11.x + gx1.z), sigm(v11.y + gx1.w));
            if (nt < 8) {
                __stcg((float4*)(g_z + m0g * H_ + nbg), r0);
                __stcg((float4*)(g_z + (m0g + 1) * H_ + nbg), r1);
            } else {
                int n2 = nbg - H_;
                r0.x *= hv0.x; r0.y *= hv0.y; r0.z *= hv0.z; r0.w *= hv0.w;
                r1.x *= hv1.x; r1.y *= hv1.y; r1.z *= hv1.z; r1.w *= hv1.w;
                __stcg((float4*)(g_rh + m0g * H_ + n2), r0);
                __stcg((float4*)(g_rh + (m0g + 1) * H_ + n2), r1);
            }
        }
        grid_sync();

        // ===================== CANDIDATE PHASE =====================
        float4 qf0 = __ldcg((const float4*)(rhrow + (size_t)pm0 * H_ + pk0));
        float4 qf1 = __ldcg((const float4*)(rhrow + (size_t)pm1 * H_ + pk0));
        const float* Cxt = g_Cx + (size_t)t * B_ * H_;
        float2 cx0 = __ldcg((const float2*)(Cxt + (size_t)m0g * H_ + nbc));
        float2 cx1 = __ldcg((const float2*)(Cxt + (size_t)(m0g + 1) * H_ + nbc));
        float2 zz0 = __ldcg((const float2*)(g_z + m0g * H_ + nbc));
        float2 zz1 = __ldcg((const float2*)(g_z + (m0g + 1) * H_ + nbc));
        float2 hh0 = __ldcg((const float2*)(g_h + m0g * H_ + nbc));
        float2 hh1 = __ldcg((const float2*)(g_h + (m0g + 1) * H_ + nbc));

        ull c0 = 0ull, c1 = 0ull;
        #pragma unroll 1
        for (int c = 0; c < 8; c++) {
            float* buf = AP + (c & 1) * AP_BUF;
            {
                int kq = pk0 >> 2;
                buf[(kq * 4 + 0) * APL + pm0] = qf0.x;
                buf[(kq * 4 + 1) * APL + pm0] = qf0.y;
                buf[(kq * 4 + 2) * APL + pm0] = qf0.z;
                buf[(kq * 4 + 3) * APL + pm0] = qf0.w;
                buf[(kq * 4 + 0) * APL + pm1] = qf1.x;
                buf[(kq * 4 + 1) * APL + pm1] = qf1.y;
                buf[(kq * 4 + 2) * APL + pm1] = qf1.z;
                buf[(kq * 4 + 3) * APL + pm1] = qf1.w;
            }
            __syncthreads();
            if (c < 7) {
                int ko = (c + 1) * 64 + pk0;
                qf0 = __ldcg((const float4*)(rhrow + (size_t)pm0 * H_ + ko));
                qf1 = __ldcg((const float4*)(rhrow + (size_t)pm1 * H_ + ko));
            }
            const float* wb = Whs + (size_t)c * 64 * WHS_LD + tx * 2;
            const float* ab = buf + ty * 2;
            #pragma unroll 16
            for (int kk = 0; kk < 64; kk++) {
                float2 a = *(const float2*)(ab + kk * APL);
                ull b = *(const ull*)(wb + kk * WHS_LD);
                FMA2(c0, splat2(a.x), b);
                FMA2(c1, splat2(a.y), b);
            }
        }
        // candidate epilogue: h update
        {
            float* hall_t = g_hall + (size_t)t * B_ * H_;
            float2 v0 = unpack2(c0), v1 = unpack2(c1);
            float cnd;
            cnd = tanh_fast(v0.x + cx0.x);
            float h00 = fmaf(zz0.x, cnd - hh0.x, hh0.x);
            cnd = tanh_fast(v0.y + cx0.y);
            float h01 = fmaf(zz0.y, cnd - hh0.y, hh0.y);
            cnd = tanh_fast(v1.x + cx1.x);
            float h10 = fmaf(zz1.x, cnd - hh1.x, hh1.x);
            cnd = tanh_fast(v1.y + cx1.y);
            float h11 = fmaf(zz1.y, cnd - hh1.y, hh1.y);
            float2 w0 = make_float2(h00, h01);
            float2 w1 = make_float2(h10, h11);
            __stcg((float2*)(g_h + m0g * H_ + nbc), w0);
            __stcg((float2*)(g_h + (m0g + 1) * H_ + nbc), w1);
            __stcg((float2*)(hall_t + (size_t)m0g * H_ + nbc), w0);
            __stcg((float2*)(hall_t + (size_t)(m0g + 1) * H_ + nbc), w1);
        }
        grid_sync();
    }
}

// ---------------------------------------------------------------------------
__global__ void gather_embed(const int* __restrict__ x,
                             const float* __restrict__ emb) {
    int idx = blockIdx.x * 256 + threadIdx.x;
    int h4  = idx & (H_ / 4 - 1);
    int row = idx >> 7;
    int b   = row & (B_ - 1);
    int s   = row >> 8;
    int tok = x[b * S_ + s];
    reinterpret_cast<float4*>(g_xe)[(size_t)row * (H_ / 4) + h4] =
        reinterpret_cast<const float4*>(emb)[(size_t)tok * (H_ / 4) + h4];
}

__global__ void copy_hfinal(float* __restrict__ out) {
    int i = blockIdx.x * 256 + threadIdx.x;
    out[i] = g_h[i];
}

// ---------------------------------------------------------------------------
extern "C" void kernel_launch(void* const* d_in, const int* in_sizes, int n_in,
                              void* d_out, int out_size) {
    (void)in_sizes; (void)n_in; (void)out_size;
    const int*   x   = (const int*)  d_in[0];
    const float* emb = (const float*)d_in[1];
    const float* Wg  = (const float*)d_in[2];
    const float* bg  = (const float*)d_in[3];
    const float* Wh  = (const float*)d_in[4];
    const float* bh  = (const float*)d_in[5];
    const float* Wo  = (const float*)d_in[6];
    const float* bo  = (const float*)d_in[7];
    float* out = (float*)d_out;

    static int smem_set = 0;
    if (!smem_set) {
        cudaFuncSetAttribute(gru_persist,
                             cudaFuncAttributeMaxDynamicSharedMemorySize,
                             PERSIST_SMEM);
        smem_set = 1;
    }

    gather_embed<<<(S_ * B_ * (H_ / 4)) / 256, 256>>>(x, emb);

    sgemm_big<<<dim3(H2_ / TBN, (S_ * B_) / TBM), 256>>>(0, Wg, H2_, bg, 0, nullptr);
    sgemm_big<<<dim3(H_  / TBN, (S_ * B_) / TBM), 256>>>(0, Wh, H2_, bh, 1, nullptr);

    gru_persist<<<128, 256, PERSIST_SMEM>>>(Wg, Wh);

    sgemm_big<<<dim3(O_ / TBN, (S_ * B_) / TBM), 256>>>(1, Wo, H_, bo, 2,
                                                        out + (size_t)B_ * H_);
    copy_hfinal<<<(B_ * H_) / 256, 256>>>(out);
}